// round 14
// baseline (speedup 1.0000x reference)
#include <cuda_runtime.h>
#include <cuda_bf16.h>
#include <cstdint>
#include <cstddef>

// ---------------------------------------------------------------------------
// Scratch (device globals; no allocation allowed anywhere)
// ---------------------------------------------------------------------------
__device__ float g_xn [16777216];   // max 16384 rows x 1024
__device__ float g_U  [67108864];   // 1024*16*4096
__device__ float g_hA [16777216];
__device__ float g_hB [16777216];
__device__ float g_bsum[4096];
__device__ float g_h0 [16384];
__device__ unsigned g_bar_count;
__device__ __nv_bfloat16 g_Ah[16777216];  // activation hi split
__device__ __nv_bfloat16 g_Al[16777216];  // activation lo split
__device__ __nv_bfloat16 g_Bh[4194304];   // weight hi split [Npad][K]
__device__ __nv_bfloat16 g_Bl[4194304];   // weight lo split

#define LN_EPS 1e-5f

__device__ __forceinline__ float sigf(float x) {
    return __fdividef(1.f, 1.f + __expf(-x));
}

__device__ __forceinline__ uint32_t smem_to_u32(const void* p) {
    uint32_t a;
    asm("{ .reg .u64 t; cvta.to.shared.u64 t, %1; cvt.u32.u64 %0, t; }"
        : "=r"(a) : "l"(p));
    return a;
}

// packed f32x2 fma: acc(lo,hi) += a(lo,hi) * b(lo,hi)
__device__ __forceinline__ void fma_f32x2(unsigned long long& acc,
                                          unsigned long long a,
                                          unsigned long long b) {
    asm("fma.rn.f32x2 %0, %1, %2, %0;" : "+l"(acc) : "l"(a), "l"(b));
}
union F2U { unsigned long long u; float2 f; };

// ---------------------------------------------------------------------------
// mma.sync / ldmatrix / cp.async primitives (base sm_103 target)
// ---------------------------------------------------------------------------
__device__ __forceinline__ void ldm_x4(uint32_t* r, uint32_t addr) {
    asm volatile("ldmatrix.sync.aligned.m8n8.x4.shared.b16 {%0,%1,%2,%3}, [%4];"
                 : "=r"(r[0]), "=r"(r[1]), "=r"(r[2]), "=r"(r[3]) : "r"(addr));
}
__device__ __forceinline__ void mma_bf16(float* d, const uint32_t* a,
                                         uint32_t b0, uint32_t b1) {
    asm volatile(
        "mma.sync.aligned.m16n8k16.row.col.f32.bf16.bf16.f32 "
        "{%0,%1,%2,%3}, {%4,%5,%6,%7}, {%8,%9}, {%0,%1,%2,%3};"
        : "+f"(d[0]), "+f"(d[1]), "+f"(d[2]), "+f"(d[3])
        : "r"(a[0]), "r"(a[1]), "r"(a[2]), "r"(a[3]), "r"(b0), "r"(b1));
}
__device__ __forceinline__ void cp_async16(uint32_t saddr, const void* gptr) {
    asm volatile("cp.async.cg.shared.global [%0], [%1], 16;"
                 :: "r"(saddr), "l"(__cvta_generic_to_global(gptr)));
}
#define CP_COMMIT()  asm volatile("cp.async.commit_group;" ::: "memory")
#define CP_WAIT(n)   asm volatile("cp.async.wait_group %0;" :: "n"(n) : "memory")

// ---------------------------------------------------------------------------
// Block reduction helper (256-thread blocks)
// ---------------------------------------------------------------------------
__device__ __forceinline__ float blockReduceSum(float v, float* shm) {
    int lane = threadIdx.x & 31, wid = threadIdx.x >> 5;
    #pragma unroll
    for (int o = 16; o; o >>= 1) v += __shfl_xor_sync(0xffffffffu, v, o);
    if (lane == 0) shm[wid] = v;
    __syncthreads();
    int nw = (blockDim.x + 31) >> 5;
    float r = (threadIdx.x < nw) ? shm[threadIdx.x] : 0.f;
    if (wid == 0) {
        #pragma unroll
        for (int o = 16; o; o >>= 1) r += __shfl_xor_sync(0xffffffffu, r, o);
        if (lane == 0) shm[0] = r;
    }
    __syncthreads();
    float total = shm[0];
    __syncthreads();
    return total;
}

// ---------------------------------------------------------------------------
// LayerNorm over last dim; optional fp32 dst (nullable) and optional bf16
// hi/lo split outputs (nullable).
// ---------------------------------------------------------------------------
__global__ __launch_bounds__(256) void ln_rows(
    const float* __restrict__ src, float* __restrict__ dst,
    __nv_bfloat16* __restrict__ hi, __nv_bfloat16* __restrict__ lo,
    const float* __restrict__ g, const float* __restrict__ be,
    int L, int Bb, int D, int srcBMajor, int dstBMajor)
{
    __shared__ float shm[32];
    int r = blockIdx.x;
    int l = r / Bb, b = r % Bb;
    const float* s = src + (srcBMajor ? ((size_t)b * L + l) : (size_t)r) * D;
    size_t drow = (dstBMajor ? ((size_t)b * L + l) : (size_t)r) * D;

    float sum = 0.f;
    for (int i = 4 * threadIdx.x; i < D; i += 1024) {
        float4 v = *(const float4*)(s + i);
        sum += (v.x + v.y) + (v.z + v.w);
    }
    float mean = blockReduceSum(sum, shm) / (float)D;

    float vs = 0.f;
    for (int i = 4 * threadIdx.x; i < D; i += 1024) {
        float4 v = *(const float4*)(s + i);
        float a = v.x - mean, bq = v.y - mean, c = v.z - mean, e = v.w - mean;
        vs += a * a + bq * bq + c * c + e * e;
    }
    float var = blockReduceSum(vs, shm) / (float)D;
    float rstd = rsqrtf(var + LN_EPS);

    for (int i = 4 * threadIdx.x; i < D; i += 1024) {
        float4 v = *(const float4*)(s + i);
        float4 gv = *(const float4*)(g + i);
        float4 bv = *(const float4*)(be + i);
        float4 o;
        o.x = (v.x - mean) * rstd * gv.x + bv.x;
        o.y = (v.y - mean) * rstd * gv.y + bv.y;
        o.z = (v.z - mean) * rstd * gv.z + bv.z;
        o.w = (v.w - mean) * rstd * gv.w + bv.w;
        if (dst) *(float4*)(dst + drow + i) = o;
        if (hi) {
            __nv_bfloat16 h0v = __float2bfloat16(o.x);
            __nv_bfloat16 h1v = __float2bfloat16(o.y);
            __nv_bfloat16 h2v = __float2bfloat16(o.z);
            __nv_bfloat16 h3v = __float2bfloat16(o.w);
            __nv_bfloat162* hp = (__nv_bfloat162*)(hi + drow + i);
            __nv_bfloat162* lp = (__nv_bfloat162*)(lo + drow + i);
            hp[0] = __nv_bfloat162(h0v, h1v);
            hp[1] = __nv_bfloat162(h2v, h3v);
            lp[0] = __nv_bfloat162(
                __float2bfloat16(o.x - __bfloat162float(h0v)),
                __float2bfloat16(o.y - __bfloat162float(h1v)));
            lp[1] = __nv_bfloat162(
                __float2bfloat16(o.z - __bfloat162float(h2v)),
                __float2bfloat16(o.w - __bfloat162float(h3v)));
        }
    }
}

// ---------------------------------------------------------------------------
// Split conversion: fp32 -> (bf16 hi, bf16 lo)
// ---------------------------------------------------------------------------
__global__ void conv_split(const float* __restrict__ x,
                           __nv_bfloat16* __restrict__ hi,
                           __nv_bfloat16* __restrict__ lo, int n)
{
    int i = blockIdx.x * blockDim.x + threadIdx.x;
    if (i >= n) return;
    float v = x[i];
    __nv_bfloat16 h = __float2bfloat16(v);
    hi[i] = h;
    lo[i] = __float2bfloat16(v - __bfloat162float(h));
}

// W[K][N] -> Bh/Bl [Npad][K] (zero rows for n >= N). grid (Npad/32, K/32), block (32,8)
__global__ void transpose_split(const float* __restrict__ W,
                                __nv_bfloat16* __restrict__ Bh,
                                __nv_bfloat16* __restrict__ Bl,
                                int K, int N)
{
    __shared__ float t[32][33];
    int n0 = blockIdx.x * 32, k0 = blockIdx.y * 32;
    int x = threadIdx.x, y = threadIdx.y;
    #pragma unroll
    for (int j = 0; j < 32; j += 8) {
        int k = k0 + y + j, n = n0 + x;
        t[y + j][x] = (n < N) ? W[(size_t)k * N + n] : 0.f;
    }
    __syncthreads();
    #pragma unroll
    for (int j = 0; j < 32; j += 8) {
        int n = n0 + y + j, k = k0 + x;
        float v = t[x][y + j];
        __nv_bfloat16 h = __float2bfloat16(v);
        Bh[(size_t)n * K + k] = h;
        Bl[(size_t)n * K + k] = __float2bfloat16(v - __bfloat162float(h));
    }
}

// ---------------------------------------------------------------------------
// Split-bf16 GEMM via mma.sync. CTA 128x128, FOUR warps (2x2), warp tile
// 64x64 -> 85 B smem traffic per HMMA (was 128) while KEEPING 2 CTAs/SM
// (regs ~200/thr x 128 thr; smem 4-stage x 24.5 KB = 98 KB per CTA).
// B fragments register-resident across the mt loop.
// ---------------------------------------------------------------------------
#define GS_A_LO  6144
#define GS_B_HI  12288
#define GS_B_LO  18432
#define GS_STAGE 24576

__global__ __launch_bounds__(128) void gemm_mma(
    const __nv_bfloat16* __restrict__ Ah, const __nv_bfloat16* __restrict__ Al,
    const __nv_bfloat16* __restrict__ Bh, const __nv_bfloat16* __restrict__ Bl,
    const float* __restrict__ bias, float* __restrict__ C,
    int K, int Nreal, int ldC)
{
    extern __shared__ char smem[];
    const uint32_t sb = smem_to_u32(smem);
    const int tid = threadIdx.x, warp = tid >> 5, lane = tid & 31;
    const int n0 = blockIdx.x * 128, m0 = blockIdx.y * 128;
    const int warpM = warp >> 1, warpN = warp & 1;      // 2 x 2, tiles 64x64
    const int S = K >> 4;                                // BK = 16

    float d[4][8][4];
    #pragma unroll
    for (int mt = 0; mt < 4; mt++)
        #pragma unroll
        for (int nt = 0; nt < 8; nt++)
            #pragma unroll
            for (int e = 0; e < 4; e++) d[mt][nt][e] = 0.f;

    // loader: 128 threads, each owns one row of all 4 arrays (2 x 16B chunks)
    auto load_stage = [&](int s, int buf) {
        const size_t kc = (size_t)s << 4;
        uint32_t so = (uint32_t)buf * GS_STAGE + tid * 48;
        size_t ga = (size_t)(m0 + tid) * K + kc;
        size_t gb = (size_t)(n0 + tid) * K + kc;
        #pragma unroll
        for (int ch = 0; ch < 2; ch++) {
            cp_async16(sb + so + ch * 16,           Ah + ga + ch * 8);
            cp_async16(sb + so + GS_A_LO + ch * 16, Al + ga + ch * 8);
            cp_async16(sb + so + GS_B_HI + ch * 16, Bh + gb + ch * 8);
            cp_async16(sb + so + GS_B_LO + ch * 16, Bl + gb + ch * 8);
        }
        CP_COMMIT();
    };

    load_stage(0, 0);
    load_stage(1, 1);
    load_stage(2, 2);

    const uint32_t off = (uint32_t)(lane & 15) * 48 + (uint32_t)(lane >> 4) * 16;

    for (int s = 0; s < S; s++) {
        if (s <= S - 3)      CP_WAIT(2);
        else if (s == S - 2) CP_WAIT(1);
        else                 CP_WAIT(0);
        __syncthreads();
        if (s + 3 < S) load_stage(s + 3, (s + 3) & 3);

        const uint32_t base  = sb + (uint32_t)(s & 3) * GS_STAGE;
        const uint32_t aBase = base + (uint32_t)(warpM * 64) * 48;
        const uint32_t bBase = base + GS_B_HI + (uint32_t)(warpN * 64) * 48;

        uint32_t bH[4][4], bL[4][4];
        #pragma unroll
        for (int ng = 0; ng < 4; ng++) {
            uint32_t bd = bBase + (uint32_t)(ng * 16) * 48 + off;
            ldm_x4(bH[ng], bd);
            ldm_x4(bL[ng], bd + (GS_B_LO - GS_B_HI));
        }
        #pragma unroll
        for (int mt = 0; mt < 4; mt++) {
            uint32_t aH[4], aL[4];
            uint32_t ad = aBase + (uint32_t)(mt * 16) * 48 + off;
            ldm_x4(aH, ad);
            ldm_x4(aL, ad + GS_A_LO);
            #pragma unroll
            for (int ng = 0; ng < 4; ng++) {
                mma_bf16(d[mt][2 * ng],     aH, bH[ng][0], bH[ng][2]);
                mma_bf16(d[mt][2 * ng + 1], aH, bH[ng][1], bH[ng][3]);
                mma_bf16(d[mt][2 * ng],     aH, bL[ng][0], bL[ng][2]);
                mma_bf16(d[mt][2 * ng + 1], aH, bL[ng][1], bL[ng][3]);
                mma_bf16(d[mt][2 * ng],     aL, bH[ng][0], bH[ng][2]);
                mma_bf16(d[mt][2 * ng + 1], aL, bH[ng][1], bH[ng][3]);
            }
        }
    }

    const int r0 = m0 + warpM * 64 + (lane >> 2);
    const int c0 = n0 + warpN * 64 + (lane & 3) * 2;
    const bool vec = ((ldC & 1) == 0);
    #pragma unroll
    for (int mt = 0; mt < 4; mt++) {
        #pragma unroll
        for (int nt = 0; nt < 8; nt++) {
            int cc = c0 + nt * 8;
            float* p0 = C + (size_t)(r0 + mt * 16) * ldC;
            float* p1 = p0 + 8 * (size_t)ldC;
            if (vec && cc + 1 < Nreal) {
                float b0v = bias ? bias[cc] : 0.f;
                float b1v = bias ? bias[cc + 1] : 0.f;
                *(float2*)(p0 + cc) = make_float2(d[mt][nt][0] + b0v, d[mt][nt][1] + b1v);
                *(float2*)(p1 + cc) = make_float2(d[mt][nt][2] + b0v, d[mt][nt][3] + b1v);
            } else {
                if (cc < Nreal) {
                    float bv = bias ? bias[cc] : 0.f;
                    p0[cc] = d[mt][nt][0] + bv;
                    p1[cc] = d[mt][nt][2] + bv;
                }
                if (cc + 1 < Nreal) {
                    float bv = bias ? bias[cc + 1] : 0.f;
                    p0[cc + 1] = d[mt][nt][1] + bv;
                    p1[cc + 1] = d[mt][nt][3] + bv;
                }
            }
        }
    }
}

// ---------------------------------------------------------------------------
// SRU scan (R11 proven form): 16384 scalar recurrences, 16-deep prefetch
// ring, grid 256x64. Optional bf16 hi/lo split output.
// ---------------------------------------------------------------------------
__global__ void sru_scan(
    const float* __restrict__ U, const float* __restrict__ res,
    const float* __restrict__ vc, const float* __restrict__ bias,
    float* __restrict__ out,
    __nv_bfloat16* __restrict__ hi, __nv_bfloat16* __restrict__ lo,
    int L, int Bb, int H, int k)
{
    int idx = blockIdx.x * blockDim.x + threadIdx.x;
    if (idx >= Bb * H) return;
    int hh = idx % H, b = idx / H;
    float vfn = -vc[hh], vrn = -vc[H + hh];
    float bf = bias[hh], br = bias[H + hh];
    float c = 0.f;

    size_t ustep = (size_t)Bb * k * H;
    size_t ubase = (size_t)b * k * H + hh;
    size_t ostep = (size_t)Bb * H;
    size_t obase = (size_t)b * H + hh;

    const float* u  = U + ubase;
    const float* rp = (k == 3) ? (res + obase) : (U + ubase + 3 * (size_t)H);
    size_t rstep    = (k == 3) ? ostep : ustep;
    float* o = out + obase;

    float pa0[16], pa1[16], pa2[16], prt[16];
    #pragma unroll
    for (int j = 0; j < 16; j++) {
        size_t uo = (size_t)j * ustep;
        pa0[j] = __ldcs(u + uo);
        pa1[j] = -(__ldcs(u + uo + H) + bf);
        pa2[j] = -(__ldcs(u + uo + 2 * (size_t)H) + br);
        prt[j] = __ldcs(rp + (size_t)j * rstep);
    }

    #pragma unroll 16
    for (int t = 0; t < L; ++t) {
        int j = t & 15;
        float a0 = pa0[j], a1n = pa1[j], a2n = pa2[j], rt = prt[j];
        int tn = (t + 16 < L) ? (t + 16) : (L - 1);
        size_t uo = (size_t)tn * ustep;
        pa0[j] = __ldcs(u + uo);
        pa1[j] = -(__ldcs(u + uo + H) + bf);
        pa2[j] = -(__ldcs(u + uo + 2 * (size_t)H) + br);
        prt[j] = __ldcs(rp + (size_t)tn * rstep);

        float e1 = __expf(fmaf(vfn, c, a1n));
        float f  = __fdividef(1.f, 1.f + e1);
        float e2 = __expf(fmaf(vrn, c, a2n));
        float r  = __fdividef(1.f, 1.f + e2);
        c = fmaf(f, c - a0, a0);
        float ov = fmaf(r, c - rt, rt);
        o[(size_t)t * ostep] = ov;
        if (hi) {
            __nv_bfloat16 hv = __float2bfloat16(ov);
            hi[obase + (size_t)t * ostep] = hv;
            lo[obase + (size_t)t * ostep] =
                __float2bfloat16(ov - __bfloat162float(hv));
        }
    }
}

__global__ void pool2(const float* __restrict__ in, float* __restrict__ out, int n)
{
    int i = blockIdx.x * blockDim.x + threadIdx.x;
    if (i >= n) return;
    int lp = i >> 14;
    size_t j = (size_t)i + (size_t)lp * 16384;
    out[i] = 0.5f * (in[j] + in[j + 16384]);
}

__global__ void addvec(const float* __restrict__ a, const float* __restrict__ b,
                       float* __restrict__ o, int n)
{
    int i = blockIdx.x * blockDim.x + threadIdx.x;
    if (i < n) o[i] = a[i] + b[i];
}

__global__ void lstm_init(float* h0)
{
    int i = blockIdx.x * blockDim.x + threadIdx.x;
    if (i < 16384) h0[i] = 0.f;
    if (i == 0) g_bar_count = 0u;
}

// ---------------------------------------------------------------------------
// Persistent LSTM (148 CTAs). f32x2 packed fma; h staged via cp.async in two
// K-halves; monotonic red.global barrier.
// ---------------------------------------------------------------------------
__global__ __launch_bounds__(256) void lstm_persist(
    const float* __restrict__ pre, const float* __restrict__ Whh,
    const float* __restrict__ h0, float* __restrict__ hout)
{
    extern __shared__ float hs[];    // 16 x 1024 floats = 64 KB
    const ulonglong2* hs2 = (const ulonglong2*)hs;
    const uint32_t hs_sb = smem_to_u32(hs);
    const int tid = threadIdx.x, bid = blockIdx.x;
    const int warp = tid >> 5, lane = tid & 31;

    int cnt, s;
    if (bid < 136) { cnt = 7; s = bid * 7; }
    else           { cnt = 6; s = 952 + (bid - 136) * 6; }
    const bool active = warp < cnt;
    const int hh = s + (active ? warp : 0);

    const ulonglong2* W2[4];
    #pragma unroll
    for (int g = 0; g < 4; g++)
        W2[g] = (const ulonglong2*)(Whh + ((size_t)g * 1024 + hh) * 1024);

    unsigned* barp;
    { unsigned* t; asm("cvta.global.u64 %0, %1;" : "=l"(t) : "l"(&g_bar_count)); barp = t; }

    float c = 0.f;

    for (int t = 0; t < 512; t++) {
        const float* hsrc = (t == 0) ? h0 : (hout + (size_t)(t - 1) * 16384);

        __syncthreads();

        #pragma unroll
        for (int half = 0; half < 2; half++) {
            #pragma unroll
            for (int j2 = 0; j2 < 8; j2++) {
                int cidx = tid + j2 * 256;
                int b = cidx >> 7, kc = cidx & 127;
                uint32_t foff = (uint32_t)(b * 1024 + half * 512 + kc * 4);
                cp_async16(hs_sb + foff * 4, hsrc + foff);
            }
            CP_COMMIT();
        }

        float pv0 = 0.f, pv1 = 0.f, pv2 = 0.f, pv3 = 0.f;
        if (active && lane < 16) {
            const float* pb = pre + (size_t)t * 65536 + (size_t)lane * 4096;
            pv0 = __ldcg(pb + hh);
            pv1 = __ldcg(pb + 1024 + hh);
            pv2 = __ldcg(pb + 2048 + hh);
            pv3 = __ldcg(pb + 3072 + hh);
        }

        unsigned long long acc2[4][16];
        #pragma unroll
        for (int g = 0; g < 4; g++)
            #pragma unroll
            for (int b = 0; b < 16; b++) acc2[g][b] = 0ull;

        CP_WAIT(1);
        __syncthreads();
        if (active) {
            #pragma unroll 1
            for (int i = lane; i < 128; i += 32) {
                ulonglong2 wq[4];
                #pragma unroll
                for (int g = 0; g < 4; g++) wq[g] = W2[g][i];
                #pragma unroll
                for (int b = 0; b < 16; b++) {
                    ulonglong2 hq = hs2[b * 256 + i];
                    #pragma unroll
                    for (int g = 0; g < 4; g++) {
                        fma_f32x2(acc2[g][b], wq[g].x, hq.x);
                        fma_f32x2(acc2[g][b], wq[g].y, hq.y);
                    }
                }
            }
        }
        CP_WAIT(0);
        __syncthreads();
        if (active) {
            #pragma unroll 1
            for (int i = 128 + lane; i < 256; i += 32) {
                ulonglong2 wq[4];
                #pragma unroll
                for (int g = 0; g < 4; g++) wq[g] = W2[g][i];
                #pragma unroll
                for (int b = 0; b < 16; b++) {
                    ulonglong2 hq = hs2[b * 256 + i];
                    #pragma unroll
                    for (int g = 0; g < 4; g++) {
                        fma_f32x2(acc2[g][b], wq[g].x, hq.x);
                        fma_f32x2(acc2[g][b], wq[g].y, hq.y);
                    }
                }
            }

            float gate[4] = {0.f, 0.f, 0.f, 0.f};
            #pragma unroll
            for (int g = 0; g < 4; g++)
                #pragma unroll
                for (int b = 0; b < 16; b++) {
                    F2U u2; u2.u = acc2[g][b];
                    float v = u2.f.x + u2.f.y;
                    #pragma unroll
                    for (int o = 16; o; o >>= 1)
                        v += __shfl_xor_sync(0xffffffffu, v, o);
                    if (lane == b) gate[g] = v;
                }

            if (lane < 16) {
                float ig = sigf(gate[0] + pv0);
                float fg = sigf(gate[1] + pv1);
                float gg = tanhf(gate[2] + pv2);
                float og = sigf(gate[3] + pv3);
                c = fg * c + ig * gg;
                float hv = og * tanhf(c);
                hout[(size_t)t * 16384 + lane * 1024 + hh] = hv;
            }
        }

        __syncthreads();
        if (tid == 0) {
            __threadfence();
            asm volatile("red.global.add.u32 [%0], %1;" :: "l"(barp), "r"(1u) : "memory");
            unsigned target = 148u * (unsigned)(t + 1);
            unsigned v;
            do {
                asm volatile("ld.global.cg.u32 %0, [%1];" : "=r"(v) : "l"(barp) : "memory");
                if (v >= target) break;
                __nanosleep(32);
            } while (true);
            __threadfence();
        }
    }
}

// ---------------------------------------------------------------------------
// Orchestration
// ---------------------------------------------------------------------------
extern "C" void kernel_launch(void* const* d_in, const int* in_sizes, int n_in,
                              void* d_out, int out_size)
{
    const float* x    = (const float*)d_in[0];
    const float* w0   = (const float*)d_in[1];
    const float* vc0  = (const float*)d_in[2];
    const float* b0   = (const float*)d_in[3];
    const float* g0   = (const float*)d_in[4];
    const float* be0  = (const float*)d_in[5];
    const float* Ws   = (const float*)d_in[6];
    const float* VCs  = (const float*)d_in[7];
    const float* Bsb  = (const float*)d_in[8];
    const float* Gs   = (const float*)d_in[9];
    const float* Bes  = (const float*)d_in[10];
    const float* Wih  = (const float*)d_in[11];
    const float* Whh  = (const float*)d_in[12];
    const float* bih  = (const float*)d_in[13];
    const float* bhh  = (const float*)d_in[14];
    const float* gh   = (const float*)d_in[15];
    const float* bhv  = (const float*)d_in[16];
    const float* Wout = (const float*)d_in[17];
    float* out = (float*)d_out;

    float *xn, *U, *hA, *hB, *bsum, *h0;
    __nv_bfloat16 *Ah, *Al, *Bh, *Bl;
    cudaGetSymbolAddress((void**)&xn,   g_xn);
    cudaGetSymbolAddress((void**)&U,    g_U);
    cudaGetSymbolAddress((void**)&hA,   g_hA);
    cudaGetSymbolAddress((void**)&hB,   g_hB);
    cudaGetSymbolAddress((void**)&bsum, g_bsum);
    cudaGetSymbolAddress((void**)&h0,   g_h0);
    cudaGetSymbolAddress((void**)&Ah,   g_Ah);
    cudaGetSymbolAddress((void**)&Al,   g_Al);
    cudaGetSymbolAddress((void**)&Bh,   g_Bh);
    cudaGetSymbolAddress((void**)&Bl,   g_Bl);

    cudaFuncSetAttribute(lstm_persist, cudaFuncAttributeMaxDynamicSharedMemorySize, 65536);
    cudaFuncSetAttribute(gemm_mma,    cudaFuncAttributeMaxDynamicSharedMemorySize, 4 * GS_STAGE);

    const int B = 16, H = 1024;
    const int GSM = 4 * GS_STAGE;

    // addvec first so the first gemm_mma lands in the profiled launch slot.
    addvec<<<16, 256>>>(bih, bhh, bsum, 4096);

    // ---- SRU layer 0: (B,1024,128) -> (1024,B,1024) ----
    ln_rows<<<16384, 256>>>(x, nullptr, Ah, Al, g0, be0, 1024, B, 128, 1, 0);
    { dim3 g(4096 / 32, 128 / 32); dim3 bl(32, 8);
      transpose_split<<<g, bl>>>(w0, Bh, Bl, 128, 4096); }
    { dim3 g(32, 128); gemm_mma<<<g, 128, GSM>>>(Ah, Al, Bh, Bl, nullptr, U, 128, 4096, 4096); }
    sru_scan<<<256, 64>>>(U, nullptr, vc0, b0, hA, nullptr, nullptr, 1024, B, H, 4);

    float* cur = hA; float* alt = hB;

    // ---- SRU layers 1-3 (L=1024) ----
    for (int i = 0; i < 3; i++) {
        ln_rows<<<16384, 256>>>(cur, xn, Ah, Al, Gs + i * H, Bes + i * H, 1024, B, H, 0, 0);
        { dim3 g(3072 / 32, 1024 / 32); dim3 bl(32, 8);
          transpose_split<<<g, bl>>>(Ws + (size_t)i * H * 3072, Bh, Bl, 1024, 3072); }
        { dim3 g(24, 128); gemm_mma<<<g, 128, GSM>>>(Ah, Al, Bh, Bl, nullptr, U, 1024, 3072, 3072); }
        sru_scan<<<256, 64>>>(U, xn, VCs + i * 2048, Bsb + i * 2048, alt, nullptr, nullptr, 1024, B, H, 3);
        float* t2 = cur; cur = alt; alt = t2;
    }

    // ---- time pooling 1024 -> 512 ----
    pool2<<<32768, 256>>>(cur, alt, 512 * 16 * 1024);
    { float* t2 = cur; cur = alt; alt = t2; }

    // ---- SRU layers 4-6 (L=512); layer 6 also emits bf16 split for LSTM ----
    for (int i = 3; i < 6; i++) {
        ln_rows<<<8192, 256>>>(cur, xn, Ah, Al, Gs + i * H, Bes + i * H, 512, B, H, 0, 0);
        { dim3 g(3072 / 32, 1024 / 32); dim3 bl(32, 8);
          transpose_split<<<g, bl>>>(Ws + (size_t)i * H * 3072, Bh, Bl, 1024, 3072); }
        { dim3 g(24, 64); gemm_mma<<<g, 128, GSM>>>(Ah, Al, Bh, Bl, nullptr, U, 1024, 3072, 3072); }
        if (i == 5)
            sru_scan<<<256, 64>>>(U, xn, VCs + i * 2048, Bsb + i * 2048, alt, Ah, Al, 512, B, H, 3);
        else
            sru_scan<<<256, 64>>>(U, xn, VCs + i * 2048, Bsb + i * 2048, alt, nullptr, nullptr, 512, B, H, 3);
        float* t2 = cur; cur = alt; alt = t2;
    }

    // ---- LSTM: pre-GEMM (activation split already produced by layer-6 scan) ----
    conv_split<<<16384, 256>>>(Wih, Bh, Bl, 4096 * 1024);
    { dim3 g(32, 64); gemm_mma<<<g, 128, GSM>>>(Ah, Al, Bh, Bl, bsum, U, 1024, 4096, 4096); }
    lstm_init<<<64, 256>>>(h0);
    lstm_persist<<<148, 256, 65536>>>(U, Whh, h0, alt);

    // ---- final LN (bf16 split only, (b,l)-major) + projection ----
    ln_rows<<<8192, 256>>>(alt, nullptr, Ah, Al, gh, bhv, 512, B, H, 0, 1);
    { dim3 g(1024 / 32, 1024 / 32); dim3 bl(32, 8);
      transpose_split<<<g, bl>>>(Wout, Bh, Bl, 1024, 1001); }
    { dim3 g(8, 64); gemm_mma<<<g, 128, GSM>>>(Ah, Al, Bh, Bl, nullptr, out, 1024, 1001, 1001); }
}

// round 15
// speedup vs baseline: 1.0824x; 1.0824x over previous
#include <cuda_runtime.h>
#include <cuda_bf16.h>
#include <cstdint>
#include <cstddef>

// ---------------------------------------------------------------------------
// Scratch (device globals; no allocation allowed anywhere)
// ---------------------------------------------------------------------------
__device__ float g_xn [16777216];   // max 16384 rows x 1024
__device__ float g_U  [67108864];   // 1024*16*4096
__device__ float g_hA [16777216];
__device__ float g_hB [16777216];
__device__ float g_bsum[4096];
__device__ float g_h0 [16384];
__device__ unsigned g_bar_count;
__device__ __nv_bfloat16 g_Ah[16777216];  // activation hi split
__device__ __nv_bfloat16 g_Al[16777216];  // activation lo split
__device__ __nv_bfloat16 g_Bh[4194304];   // weight hi split [Npad][K]
__device__ __nv_bfloat16 g_Bl[4194304];   // weight lo split

#define LN_EPS 1e-5f

__device__ __forceinline__ float sigf(float x) {
    return __fdividef(1.f, 1.f + __expf(-x));
}

__device__ __forceinline__ uint32_t smem_to_u32(const void* p) {
    uint32_t a;
    asm("{ .reg .u64 t; cvta.to.shared.u64 t, %1; cvt.u32.u64 %0, t; }"
        : "=r"(a) : "l"(p));
    return a;
}

// packed f32x2 fma: acc(lo,hi) += a(lo,hi) * b(lo,hi)
__device__ __forceinline__ void fma_f32x2(unsigned long long& acc,
                                          unsigned long long a,
                                          unsigned long long b) {
    asm("fma.rn.f32x2 %0, %1, %2, %0;" : "+l"(acc) : "l"(a), "l"(b));
}
union F2U { unsigned long long u; float2 f; };

// ---------------------------------------------------------------------------
// mma.sync / ldmatrix / cp.async primitives (base sm_103 target)
// ---------------------------------------------------------------------------
__device__ __forceinline__ void ldm_x4(uint32_t* r, uint32_t addr) {
    asm volatile("ldmatrix.sync.aligned.m8n8.x4.shared.b16 {%0,%1,%2,%3}, [%4];"
                 : "=r"(r[0]), "=r"(r[1]), "=r"(r[2]), "=r"(r[3]) : "r"(addr));
}
__device__ __forceinline__ void mma_bf16(float* d, const uint32_t* a,
                                         uint32_t b0, uint32_t b1) {
    asm volatile(
        "mma.sync.aligned.m16n8k16.row.col.f32.bf16.bf16.f32 "
        "{%0,%1,%2,%3}, {%4,%5,%6,%7}, {%8,%9}, {%0,%1,%2,%3};"
        : "+f"(d[0]), "+f"(d[1]), "+f"(d[2]), "+f"(d[3])
        : "r"(a[0]), "r"(a[1]), "r"(a[2]), "r"(a[3]), "r"(b0), "r"(b1));
}
__device__ __forceinline__ void cp_async16(uint32_t saddr, const void* gptr) {
    asm volatile("cp.async.cg.shared.global [%0], [%1], 16;"
                 :: "r"(saddr), "l"(__cvta_generic_to_global(gptr)));
}
#define CP_COMMIT()  asm volatile("cp.async.commit_group;" ::: "memory")
#define CP_WAIT(n)   asm volatile("cp.async.wait_group %0;" :: "n"(n) : "memory")

// ---------------------------------------------------------------------------
// Block reduction helper (256-thread blocks)
// ---------------------------------------------------------------------------
__device__ __forceinline__ float blockReduceSum(float v, float* shm) {
    int lane = threadIdx.x & 31, wid = threadIdx.x >> 5;
    #pragma unroll
    for (int o = 16; o; o >>= 1) v += __shfl_xor_sync(0xffffffffu, v, o);
    if (lane == 0) shm[wid] = v;
    __syncthreads();
    int nw = (blockDim.x + 31) >> 5;
    float r = (threadIdx.x < nw) ? shm[threadIdx.x] : 0.f;
    if (wid == 0) {
        #pragma unroll
        for (int o = 16; o; o >>= 1) r += __shfl_xor_sync(0xffffffffu, r, o);
        if (lane == 0) shm[0] = r;
    }
    __syncthreads();
    float total = shm[0];
    __syncthreads();
    return total;
}

// ---------------------------------------------------------------------------
// LayerNorm over last dim; optional fp32 dst (nullable) and optional bf16
// hi/lo split outputs (nullable).
// ---------------------------------------------------------------------------
__global__ __launch_bounds__(256) void ln_rows(
    const float* __restrict__ src, float* __restrict__ dst,
    __nv_bfloat16* __restrict__ hi, __nv_bfloat16* __restrict__ lo,
    const float* __restrict__ g, const float* __restrict__ be,
    int L, int Bb, int D, int srcBMajor, int dstBMajor)
{
    __shared__ float shm[32];
    int r = blockIdx.x;
    int l = r / Bb, b = r % Bb;
    const float* s = src + (srcBMajor ? ((size_t)b * L + l) : (size_t)r) * D;
    size_t drow = (dstBMajor ? ((size_t)b * L + l) : (size_t)r) * D;

    float sum = 0.f;
    for (int i = 4 * threadIdx.x; i < D; i += 1024) {
        float4 v = *(const float4*)(s + i);
        sum += (v.x + v.y) + (v.z + v.w);
    }
    float mean = blockReduceSum(sum, shm) / (float)D;

    float vs = 0.f;
    for (int i = 4 * threadIdx.x; i < D; i += 1024) {
        float4 v = *(const float4*)(s + i);
        float a = v.x - mean, bq = v.y - mean, c = v.z - mean, e = v.w - mean;
        vs += a * a + bq * bq + c * c + e * e;
    }
    float var = blockReduceSum(vs, shm) / (float)D;
    float rstd = rsqrtf(var + LN_EPS);

    for (int i = 4 * threadIdx.x; i < D; i += 1024) {
        float4 v = *(const float4*)(s + i);
        float4 gv = *(const float4*)(g + i);
        float4 bv = *(const float4*)(be + i);
        float4 o;
        o.x = (v.x - mean) * rstd * gv.x + bv.x;
        o.y = (v.y - mean) * rstd * gv.y + bv.y;
        o.z = (v.z - mean) * rstd * gv.z + bv.z;
        o.w = (v.w - mean) * rstd * gv.w + bv.w;
        if (dst) *(float4*)(dst + drow + i) = o;
        if (hi) {
            __nv_bfloat16 h0v = __float2bfloat16(o.x);
            __nv_bfloat16 h1v = __float2bfloat16(o.y);
            __nv_bfloat16 h2v = __float2bfloat16(o.z);
            __nv_bfloat16 h3v = __float2bfloat16(o.w);
            __nv_bfloat162* hp = (__nv_bfloat162*)(hi + drow + i);
            __nv_bfloat162* lp = (__nv_bfloat162*)(lo + drow + i);
            hp[0] = __nv_bfloat162(h0v, h1v);
            hp[1] = __nv_bfloat162(h2v, h3v);
            lp[0] = __nv_bfloat162(
                __float2bfloat16(o.x - __bfloat162float(h0v)),
                __float2bfloat16(o.y - __bfloat162float(h1v)));
            lp[1] = __nv_bfloat162(
                __float2bfloat16(o.z - __bfloat162float(h2v)),
                __float2bfloat16(o.w - __bfloat162float(h3v)));
        }
    }
}

// ---------------------------------------------------------------------------
// Split conversion: fp32 -> (bf16 hi, bf16 lo)
// ---------------------------------------------------------------------------
__global__ void conv_split(const float* __restrict__ x,
                           __nv_bfloat16* __restrict__ hi,
                           __nv_bfloat16* __restrict__ lo, int n)
{
    int i = blockIdx.x * blockDim.x + threadIdx.x;
    if (i >= n) return;
    float v = x[i];
    __nv_bfloat16 h = __float2bfloat16(v);
    hi[i] = h;
    lo[i] = __float2bfloat16(v - __bfloat162float(h));
}

// W[K][N] -> Bh/Bl [Npad][K] (zero rows for n >= N). grid (Npad/32, K/32), block (32,8)
__global__ void transpose_split(const float* __restrict__ W,
                                __nv_bfloat16* __restrict__ Bh,
                                __nv_bfloat16* __restrict__ Bl,
                                int K, int N)
{
    __shared__ float t[32][33];
    int n0 = blockIdx.x * 32, k0 = blockIdx.y * 32;
    int x = threadIdx.x, y = threadIdx.y;
    #pragma unroll
    for (int j = 0; j < 32; j += 8) {
        int k = k0 + y + j, n = n0 + x;
        t[y + j][x] = (n < N) ? W[(size_t)k * N + n] : 0.f;
    }
    __syncthreads();
    #pragma unroll
    for (int j = 0; j < 32; j += 8) {
        int n = n0 + y + j, k = k0 + x;
        float v = t[x][y + j];
        __nv_bfloat16 h = __float2bfloat16(v);
        Bh[(size_t)n * K + k] = h;
        Bl[(size_t)n * K + k] = __float2bfloat16(v - __bfloat162float(h));
    }
}

// ---------------------------------------------------------------------------
// Split-bf16 GEMM via mma.sync — PROVEN R11 config: CTA 128x128, BK=16,
// 8 warps (2x4), warp tile 64x32, 4-stage ring, 2 CTAs/SM. Best measured:
// tensor 40.4%, 209 us on the profiled layer. DO NOT restructure blind
// (R12: 1 CTA/SM regressed; R14: 4-warp CTA regressed — issue-latency bound,
// tensor% tracks warps/SM).
// ---------------------------------------------------------------------------
#define GS_A_LO  6144
#define GS_B_HI  12288
#define GS_B_LO  18432
#define GS_STAGE 24576

__global__ __launch_bounds__(256) void gemm_mma(
    const __nv_bfloat16* __restrict__ Ah, const __nv_bfloat16* __restrict__ Al,
    const __nv_bfloat16* __restrict__ Bh, const __nv_bfloat16* __restrict__ Bl,
    const float* __restrict__ bias, float* __restrict__ C,
    int K, int Nreal, int ldC)
{
    extern __shared__ char smem[];
    const uint32_t sb = smem_to_u32(smem);
    const int tid = threadIdx.x, warp = tid >> 5, lane = tid & 31;
    const int n0 = blockIdx.x * 128, m0 = blockIdx.y * 128;
    const int warpM = warp >> 2, warpN = warp & 3;      // 2 x 4
    const int S = K >> 4;                                // BK = 16

    float d[4][4][4];
    #pragma unroll
    for (int mt = 0; mt < 4; mt++)
        #pragma unroll
        for (int nt = 0; nt < 4; nt++)
            #pragma unroll
            for (int e = 0; e < 4; e++) d[mt][nt][e] = 0.f;

    const int lrow = tid >> 1, lc = tid & 1;
    auto load_stage = [&](int s, int buf) {
        const size_t kc = ((size_t)s << 4) + lc * 8;
        uint32_t so = (uint32_t)buf * GS_STAGE + lrow * 48 + lc * 16;
        size_t ga = (size_t)(m0 + lrow) * K + kc;
        size_t gb = (size_t)(n0 + lrow) * K + kc;
        cp_async16(sb + so,           Ah + ga);
        cp_async16(sb + so + GS_A_LO, Al + ga);
        cp_async16(sb + so + GS_B_HI, Bh + gb);
        cp_async16(sb + so + GS_B_LO, Bl + gb);
        CP_COMMIT();
    };

    load_stage(0, 0);
    load_stage(1, 1);
    load_stage(2, 2);

    const uint32_t off = (uint32_t)(lane & 15) * 48 + (uint32_t)(lane >> 4) * 16;

    for (int s = 0; s < S; s++) {
        if (s <= S - 3)      CP_WAIT(2);
        else if (s == S - 2) CP_WAIT(1);
        else                 CP_WAIT(0);
        __syncthreads();
        if (s + 3 < S) load_stage(s + 3, (s + 3) & 3);

        const uint32_t base  = sb + (uint32_t)(s & 3) * GS_STAGE;
        const uint32_t aBase = base + (uint32_t)(warpM * 64) * 48;
        const uint32_t bBase = base + GS_B_HI + (uint32_t)(warpN * 32) * 48;

        uint32_t aH[4][4], aL[4][4], bH[2][4], bL[2][4];
        #pragma unroll
        for (int mt = 0; mt < 4; mt++) {
            uint32_t ad = aBase + (uint32_t)(mt * 16) * 48 + off;
            ldm_x4(aH[mt], ad);
            ldm_x4(aL[mt], ad + GS_A_LO);
        }
        #pragma unroll
        for (int ng = 0; ng < 2; ng++) {
            uint32_t bd = bBase + (uint32_t)(ng * 16) * 48 + off;
            ldm_x4(bH[ng], bd);
            ldm_x4(bL[ng], bd + (GS_B_LO - GS_B_HI));
        }
        #pragma unroll
        for (int mt = 0; mt < 4; mt++)
            #pragma unroll
            for (int ng = 0; ng < 2; ng++) {
                mma_bf16(d[mt][2 * ng],     aH[mt], bH[ng][0], bH[ng][2]);
                mma_bf16(d[mt][2 * ng + 1], aH[mt], bH[ng][1], bH[ng][3]);
                mma_bf16(d[mt][2 * ng],     aH[mt], bL[ng][0], bL[ng][2]);
                mma_bf16(d[mt][2 * ng + 1], aH[mt], bL[ng][1], bL[ng][3]);
                mma_bf16(d[mt][2 * ng],     aL[mt], bH[ng][0], bH[ng][2]);
                mma_bf16(d[mt][2 * ng + 1], aL[mt], bH[ng][1], bH[ng][3]);
            }
    }

    const int r0 = m0 + warpM * 64 + (lane >> 2);
    const int c0 = n0 + warpN * 32 + (lane & 3) * 2;
    const bool vec = ((ldC & 1) == 0);
    #pragma unroll
    for (int mt = 0; mt < 4; mt++) {
        #pragma unroll
        for (int nt = 0; nt < 4; nt++) {
            int cc = c0 + nt * 8;
            float* p0 = C + (size_t)(r0 + mt * 16) * ldC;
            float* p1 = p0 + 8 * (size_t)ldC;
            if (vec && cc + 1 < Nreal) {
                float b0v = bias ? bias[cc] : 0.f;
                float b1v = bias ? bias[cc + 1] : 0.f;
                *(float2*)(p0 + cc) = make_float2(d[mt][nt][0] + b0v, d[mt][nt][1] + b1v);
                *(float2*)(p1 + cc) = make_float2(d[mt][nt][2] + b0v, d[mt][nt][3] + b1v);
            } else {
                if (cc < Nreal) {
                    float bv = bias ? bias[cc] : 0.f;
                    p0[cc] = d[mt][nt][0] + bv;
                    p1[cc] = d[mt][nt][2] + bv;
                }
                if (cc + 1 < Nreal) {
                    float bv = bias ? bias[cc + 1] : 0.f;
                    p0[cc + 1] = d[mt][nt][1] + bv;
                    p1[cc + 1] = d[mt][nt][3] + bv;
                }
            }
        }
    }
}

// ---------------------------------------------------------------------------
// SRU scan (R11 proven form): 16384 scalar recurrences, 16-deep prefetch
// ring, grid 256x64. Optional bf16 hi/lo split output (pre-LSTM layer).
// ---------------------------------------------------------------------------
__global__ void sru_scan(
    const float* __restrict__ U, const float* __restrict__ res,
    const float* __restrict__ vc, const float* __restrict__ bias,
    float* __restrict__ out,
    __nv_bfloat16* __restrict__ hi, __nv_bfloat16* __restrict__ lo,
    int L, int Bb, int H, int k)
{
    int idx = blockIdx.x * blockDim.x + threadIdx.x;
    if (idx >= Bb * H) return;
    int hh = idx % H, b = idx / H;
    float vfn = -vc[hh], vrn = -vc[H + hh];
    float bf = bias[hh], br = bias[H + hh];
    float c = 0.f;

    size_t ustep = (size_t)Bb * k * H;
    size_t ubase = (size_t)b * k * H + hh;
    size_t ostep = (size_t)Bb * H;
    size_t obase = (size_t)b * H + hh;

    const float* u  = U + ubase;
    const float* rp = (k == 3) ? (res + obase) : (U + ubase + 3 * (size_t)H);
    size_t rstep    = (k == 3) ? ostep : ustep;
    float* o = out + obase;

    float pa0[16], pa1[16], pa2[16], prt[16];
    #pragma unroll
    for (int j = 0; j < 16; j++) {
        size_t uo = (size_t)j * ustep;
        pa0[j] = __ldcs(u + uo);
        pa1[j] = -(__ldcs(u + uo + H) + bf);
        pa2[j] = -(__ldcs(u + uo + 2 * (size_t)H) + br);
        prt[j] = __ldcs(rp + (size_t)j * rstep);
    }

    #pragma unroll 16
    for (int t = 0; t < L; ++t) {
        int j = t & 15;
        float a0 = pa0[j], a1n = pa1[j], a2n = pa2[j], rt = prt[j];
        int tn = (t + 16 < L) ? (t + 16) : (L - 1);
        size_t uo = (size_t)tn * ustep;
        pa0[j] = __ldcs(u + uo);
        pa1[j] = -(__ldcs(u + uo + H) + bf);
        pa2[j] = -(__ldcs(u + uo + 2 * (size_t)H) + br);
        prt[j] = __ldcs(rp + (size_t)tn * rstep);

        float e1 = __expf(fmaf(vfn, c, a1n));
        float f  = __fdividef(1.f, 1.f + e1);
        float e2 = __expf(fmaf(vrn, c, a2n));
        float r  = __fdividef(1.f, 1.f + e2);
        c = fmaf(f, c - a0, a0);
        float ov = fmaf(r, c - rt, rt);
        o[(size_t)t * ostep] = ov;
        if (hi) {
            __nv_bfloat16 hv = __float2bfloat16(ov);
            hi[obase + (size_t)t * ostep] = hv;
            lo[obase + (size_t)t * ostep] =
                __float2bfloat16(ov - __bfloat162float(hv));
        }
    }
}

__global__ void pool2(const float* __restrict__ in, float* __restrict__ out, int n)
{
    int i = blockIdx.x * blockDim.x + threadIdx.x;
    if (i >= n) return;
    int lp = i >> 14;
    size_t j = (size_t)i + (size_t)lp * 16384;
    out[i] = 0.5f * (in[j] + in[j + 16384]);
}

__global__ void addvec(const float* __restrict__ a, const float* __restrict__ b,
                       float* __restrict__ o, int n)
{
    int i = blockIdx.x * blockDim.x + threadIdx.x;
    if (i < n) o[i] = a[i] + b[i];
}

__global__ void lstm_init(float* h0)
{
    int i = blockIdx.x * blockDim.x + threadIdx.x;
    if (i < 16384) h0[i] = 0.f;
    if (i == 0) g_bar_count = 0u;
}

// ---------------------------------------------------------------------------
// Persistent LSTM (148 CTAs). f32x2 packed fma; h staged via cp.async in two
// K-halves; monotonic red.global barrier.
// ---------------------------------------------------------------------------
__global__ __launch_bounds__(256) void lstm_persist(
    const float* __restrict__ pre, const float* __restrict__ Whh,
    const float* __restrict__ h0, float* __restrict__ hout)
{
    extern __shared__ float hs[];    // 16 x 1024 floats = 64 KB
    const ulonglong2* hs2 = (const ulonglong2*)hs;
    const uint32_t hs_sb = smem_to_u32(hs);
    const int tid = threadIdx.x, bid = blockIdx.x;
    const int warp = tid >> 5, lane = tid & 31;

    int cnt, s;
    if (bid < 136) { cnt = 7; s = bid * 7; }
    else           { cnt = 6; s = 952 + (bid - 136) * 6; }
    const bool active = warp < cnt;
    const int hh = s + (active ? warp : 0);

    const ulonglong2* W2[4];
    #pragma unroll
    for (int g = 0; g < 4; g++)
        W2[g] = (const ulonglong2*)(Whh + ((size_t)g * 1024 + hh) * 1024);

    unsigned* barp;
    { unsigned* t; asm("cvta.global.u64 %0, %1;" : "=l"(t) : "l"(&g_bar_count)); barp = t; }

    float c = 0.f;

    for (int t = 0; t < 512; t++) {
        const float* hsrc = (t == 0) ? h0 : (hout + (size_t)(t - 1) * 16384);

        __syncthreads();

        #pragma unroll
        for (int half = 0; half < 2; half++) {
            #pragma unroll
            for (int j2 = 0; j2 < 8; j2++) {
                int cidx = tid + j2 * 256;
                int b = cidx >> 7, kc = cidx & 127;
                uint32_t foff = (uint32_t)(b * 1024 + half * 512 + kc * 4);
                cp_async16(hs_sb + foff * 4, hsrc + foff);
            }
            CP_COMMIT();
        }

        float pv0 = 0.f, pv1 = 0.f, pv2 = 0.f, pv3 = 0.f;
        if (active && lane < 16) {
            const float* pb = pre + (size_t)t * 65536 + (size_t)lane * 4096;
            pv0 = __ldcg(pb + hh);
            pv1 = __ldcg(pb + 1024 + hh);
            pv2 = __ldcg(pb + 2048 + hh);
            pv3 = __ldcg(pb + 3072 + hh);
        }

        unsigned long long acc2[4][16];
        #pragma unroll
        for (int g = 0; g < 4; g++)
            #pragma unroll
            for (int b = 0; b < 16; b++) acc2[g][b] = 0ull;

        CP_WAIT(1);
        __syncthreads();
        if (active) {
            #pragma unroll 1
            for (int i = lane; i < 128; i += 32) {
                ulonglong2 wq[4];
                #pragma unroll
                for (int g = 0; g < 4; g++) wq[g] = W2[g][i];
                #pragma unroll
                for (int b = 0; b < 16; b++) {
                    ulonglong2 hq = hs2[b * 256 + i];
                    #pragma unroll
                    for (int g = 0; g < 4; g++) {
                        fma_f32x2(acc2[g][b], wq[g].x, hq.x);
                        fma_f32x2(acc2[g][b], wq[g].y, hq.y);
                    }
                }
            }
        }
        CP_WAIT(0);
        __syncthreads();
        if (active) {
            #pragma unroll 1
            for (int i = 128 + lane; i < 256; i += 32) {
                ulonglong2 wq[4];
                #pragma unroll
                for (int g = 0; g < 4; g++) wq[g] = W2[g][i];
                #pragma unroll
                for (int b = 0; b < 16; b++) {
                    ulonglong2 hq = hs2[b * 256 + i];
                    #pragma unroll
                    for (int g = 0; g < 4; g++) {
                        fma_f32x2(acc2[g][b], wq[g].x, hq.x);
                        fma_f32x2(acc2[g][b], wq[g].y, hq.y);
                    }
                }
            }

            float gate[4] = {0.f, 0.f, 0.f, 0.f};
            #pragma unroll
            for (int g = 0; g < 4; g++)
                #pragma unroll
                for (int b = 0; b < 16; b++) {
                    F2U u2; u2.u = acc2[g][b];
                    float v = u2.f.x + u2.f.y;
                    #pragma unroll
                    for (int o = 16; o; o >>= 1)
                        v += __shfl_xor_sync(0xffffffffu, v, o);
                    if (lane == b) gate[g] = v;
                }

            if (lane < 16) {
                float ig = sigf(gate[0] + pv0);
                float fg = sigf(gate[1] + pv1);
                float gg = tanhf(gate[2] + pv2);
                float og = sigf(gate[3] + pv3);
                c = fg * c + ig * gg;
                float hv = og * tanhf(c);
                hout[(size_t)t * 16384 + lane * 1024 + hh] = hv;
            }
        }

        __syncthreads();
        if (tid == 0) {
            __threadfence();
            asm volatile("red.global.add.u32 [%0], %1;" :: "l"(barp), "r"(1u) : "memory");
            unsigned target = 148u * (unsigned)(t + 1);
            unsigned v;
            do {
                asm volatile("ld.global.cg.u32 %0, [%1];" : "=r"(v) : "l"(barp) : "memory");
                if (v >= target) break;
                __nanosleep(32);
            } while (true);
            __threadfence();
        }
    }
}

// ---------------------------------------------------------------------------
// Orchestration
// ---------------------------------------------------------------------------
extern "C" void kernel_launch(void* const* d_in, const int* in_sizes, int n_in,
                              void* d_out, int out_size)
{
    const float* x    = (const float*)d_in[0];
    const float* w0   = (const float*)d_in[1];
    const float* vc0  = (const float*)d_in[2];
    const float* b0   = (const float*)d_in[3];
    const float* g0   = (const float*)d_in[4];
    const float* be0  = (const float*)d_in[5];
    const float* Ws   = (const float*)d_in[6];
    const float* VCs  = (const float*)d_in[7];
    const float* Bsb  = (const float*)d_in[8];
    const float* Gs   = (const float*)d_in[9];
    const float* Bes  = (const float*)d_in[10];
    const float* Wih  = (const float*)d_in[11];
    const float* Whh  = (const float*)d_in[12];
    const float* bih  = (const float*)d_in[13];
    const float* bhh  = (const float*)d_in[14];
    const float* gh   = (const float*)d_in[15];
    const float* bhv  = (const float*)d_in[16];
    const float* Wout = (const float*)d_in[17];
    float* out = (float*)d_out;

    float *xn, *U, *hA, *hB, *bsum, *h0;
    __nv_bfloat16 *Ah, *Al, *Bh, *Bl;
    cudaGetSymbolAddress((void**)&xn,   g_xn);
    cudaGetSymbolAddress((void**)&U,    g_U);
    cudaGetSymbolAddress((void**)&hA,   g_hA);
    cudaGetSymbolAddress((void**)&hB,   g_hB);
    cudaGetSymbolAddress((void**)&bsum, g_bsum);
    cudaGetSymbolAddress((void**)&h0,   g_h0);
    cudaGetSymbolAddress((void**)&Ah,   g_Ah);
    cudaGetSymbolAddress((void**)&Al,   g_Al);
    cudaGetSymbolAddress((void**)&Bh,   g_Bh);
    cudaGetSymbolAddress((void**)&Bl,   g_Bl);

    cudaFuncSetAttribute(lstm_persist, cudaFuncAttributeMaxDynamicSharedMemorySize, 65536);
    cudaFuncSetAttribute(gemm_mma,    cudaFuncAttributeMaxDynamicSharedMemorySize, 4 * GS_STAGE);

    const int B = 16, H = 1024;
    const int GSM = 4 * GS_STAGE;

    // addvec first so the first gemm_mma lands in the profiled launch slot.
    addvec<<<16, 256>>>(bih, bhh, bsum, 4096);

    // ---- SRU layer 0: (B,1024,128) -> (1024,B,1024) ----
    ln_rows<<<16384, 256>>>(x, nullptr, Ah, Al, g0, be0, 1024, B, 128, 1, 0);
    { dim3 g(4096 / 32, 128 / 32); dim3 bl(32, 8);
      transpose_split<<<g, bl>>>(w0, Bh, Bl, 128, 4096); }
    { dim3 g(32, 128); gemm_mma<<<g, 256, GSM>>>(Ah, Al, Bh, Bl, nullptr, U, 128, 4096, 4096); }
    sru_scan<<<256, 64>>>(U, nullptr, vc0, b0, hA, nullptr, nullptr, 1024, B, H, 4);

    float* cur = hA; float* alt = hB;

    // ---- SRU layers 1-3 (L=1024) ----
    for (int i = 0; i < 3; i++) {
        ln_rows<<<16384, 256>>>(cur, xn, Ah, Al, Gs + i * H, Bes + i * H, 1024, B, H, 0, 0);
        { dim3 g(3072 / 32, 1024 / 32); dim3 bl(32, 8);
          transpose_split<<<g, bl>>>(Ws + (size_t)i * H * 3072, Bh, Bl, 1024, 3072); }
        { dim3 g(24, 128); gemm_mma<<<g, 256, GSM>>>(Ah, Al, Bh, Bl, nullptr, U, 1024, 3072, 3072); }
        sru_scan<<<256, 64>>>(U, xn, VCs + i * 2048, Bsb + i * 2048, alt, nullptr, nullptr, 1024, B, H, 3);
        float* t2 = cur; cur = alt; alt = t2;
    }

    // ---- time pooling 1024 -> 512 ----
    pool2<<<32768, 256>>>(cur, alt, 512 * 16 * 1024);
    { float* t2 = cur; cur = alt; alt = t2; }

    // ---- SRU layers 4-6 (L=512); layer 6 also emits bf16 split for LSTM ----
    for (int i = 3; i < 6; i++) {
        ln_rows<<<8192, 256>>>(cur, xn, Ah, Al, Gs + i * H, Bes + i * H, 512, B, H, 0, 0);
        { dim3 g(3072 / 32, 1024 / 32); dim3 bl(32, 8);
          transpose_split<<<g, bl>>>(Ws + (size_t)i * H * 3072, Bh, Bl, 1024, 3072); }
        { dim3 g(24, 64); gemm_mma<<<g, 256, GSM>>>(Ah, Al, Bh, Bl, nullptr, U, 1024, 3072, 3072); }
        if (i == 5)
            sru_scan<<<256, 64>>>(U, xn, VCs + i * 2048, Bsb + i * 2048, alt, Ah, Al, 512, B, H, 3);
        else
            sru_scan<<<256, 64>>>(U, xn, VCs + i * 2048, Bsb + i * 2048, alt, nullptr, nullptr, 512, B, H, 3);
        float* t2 = cur; cur = alt; alt = t2;
    }

    // ---- LSTM: pre-GEMM (activation split already produced by layer-6 scan) ----
    conv_split<<<16384, 256>>>(Wih, Bh, Bl, 4096 * 1024);
    { dim3 g(32, 64); gemm_mma<<<g, 256, GSM>>>(Ah, Al, Bh, Bl, bsum, U, 1024, 4096, 4096); }
    lstm_init<<<64, 256>>>(h0);
    lstm_persist<<<148, 256, 65536>>>(U, Whh, h0, alt);

    // ---- final LN (bf16 split only, (b,l)-major) + projection ----
    ln_rows<<<8192, 256>>>(alt, nullptr, Ah, Al, gh, bhv, 512, B, H, 0, 1);
    { dim3 g(1024 / 32, 1024 / 32); dim3 bl(32, 8);
      transpose_split<<<g, bl>>>(Wout, Bh, Bl, 1024, 1001); }
    { dim3 g(8, 64); gemm_mma<<<g, 256, GSM>>>(Ah, Al, Bh, Bl, nullptr, out, 1024, 1001, 1001); }
}

// round 17
// speedup vs baseline: 1.1096x; 1.0252x over previous
#include <cuda_runtime.h>
#include <cuda_bf16.h>
#include <cuda_fp16.h>
#include <cstdint>
#include <cstddef>

// ---------------------------------------------------------------------------
// Scratch (device globals; no allocation allowed anywhere)
// ---------------------------------------------------------------------------
__device__ float g_xn [16777216];   // max 16384 rows x 1024
__device__ float g_U  [67108864];   // 1024*16*4096
__device__ float g_hA [16777216];
__device__ float g_hB [16777216];
__device__ float g_bsum[4096];
__device__ float g_h0 [16384];
__device__ unsigned g_bar_count;
__device__ __nv_bfloat16 g_Ah[16777216];  // activation hi split (16-bit, re-punned for fp16)
__device__ __nv_bfloat16 g_Al[16777216];  // activation lo split
__device__ __nv_bfloat16 g_Bh[4194304];   // weight hi split [Npad][K]
__device__ __nv_bfloat16 g_Bl[4194304];   // weight lo split

#define LN_EPS 1e-5f

__device__ __forceinline__ float sigf(float x) {
    return __fdividef(1.f, 1.f + __expf(-x));
}

__device__ __forceinline__ uint32_t smem_to_u32(const void* p) {
    uint32_t a;
    asm("{ .reg .u64 t; cvta.to.shared.u64 t, %1; cvt.u32.u64 %0, t; }"
        : "=r"(a) : "l"(p));
    return a;
}

// packed f32x2 fma: acc(lo,hi) += a(lo,hi) * b(lo,hi)
__device__ __forceinline__ void fma_f32x2(unsigned long long& acc,
                                          unsigned long long a,
                                          unsigned long long b) {
    asm("fma.rn.f32x2 %0, %1, %2, %0;" : "+l"(acc) : "l"(a), "l"(b));
}
union F2U { unsigned long long u; float2 f; };

// ---------------------------------------------------------------------------
// mma.sync / ldmatrix / cp.async primitives (base sm_103 target)
// ---------------------------------------------------------------------------
__device__ __forceinline__ void ldm_x4(uint32_t* r, uint32_t addr) {
    asm volatile("ldmatrix.sync.aligned.m8n8.x4.shared.b16 {%0,%1,%2,%3}, [%4];"
                 : "=r"(r[0]), "=r"(r[1]), "=r"(r[2]), "=r"(r[3]) : "r"(addr));
}
__device__ __forceinline__ void mma_bf16(float* d, const uint32_t* a,
                                         uint32_t b0, uint32_t b1) {
    asm volatile(
        "mma.sync.aligned.m16n8k16.row.col.f32.bf16.bf16.f32 "
        "{%0,%1,%2,%3}, {%4,%5,%6,%7}, {%8,%9}, {%0,%1,%2,%3};"
        : "+f"(d[0]), "+f"(d[1]), "+f"(d[2]), "+f"(d[3])
        : "r"(a[0]), "r"(a[1]), "r"(a[2]), "r"(a[3]), "r"(b0), "r"(b1));
}
__device__ __forceinline__ void mma_f16(float* d, const uint32_t* a,
                                        uint32_t b0, uint32_t b1) {
    asm volatile(
        "mma.sync.aligned.m16n8k16.row.col.f32.f16.f16.f32 "
        "{%0,%1,%2,%3}, {%4,%5,%6,%7}, {%8,%9}, {%0,%1,%2,%3};"
        : "+f"(d[0]), "+f"(d[1]), "+f"(d[2]), "+f"(d[3])
        : "r"(a[0]), "r"(a[1]), "r"(a[2]), "r"(a[3]), "r"(b0), "r"(b1));
}
__device__ __forceinline__ void cp_async16(uint32_t saddr, const void* gptr) {
    asm volatile("cp.async.cg.shared.global [%0], [%1], 16;"
                 :: "r"(saddr), "l"(__cvta_generic_to_global(gptr)));
}
#define CP_COMMIT()  asm volatile("cp.async.commit_group;" ::: "memory")
#define CP_WAIT(n)   asm volatile("cp.async.wait_group %0;" :: "n"(n) : "memory")

// ---------------------------------------------------------------------------
// Block reduction helper (256-thread blocks)
// ---------------------------------------------------------------------------
__device__ __forceinline__ float blockReduceSum(float v, float* shm) {
    int lane = threadIdx.x & 31, wid = threadIdx.x >> 5;
    #pragma unroll
    for (int o = 16; o; o >>= 1) v += __shfl_xor_sync(0xffffffffu, v, o);
    if (lane == 0) shm[wid] = v;
    __syncthreads();
    int nw = (blockDim.x + 31) >> 5;
    float r = (threadIdx.x < nw) ? shm[threadIdx.x] : 0.f;
    if (wid == 0) {
        #pragma unroll
        for (int o = 16; o; o >>= 1) r += __shfl_xor_sync(0xffffffffu, r, o);
        if (lane == 0) shm[0] = r;
    }
    __syncthreads();
    float total = shm[0];
    __syncthreads();
    return total;
}

// ---------------------------------------------------------------------------
// LayerNorm. outMode: 0 = fp32 dst only; 1 = bf16 hi/lo pair (+opt dst);
// 2 = fp16 single (hi reinterpreted as __half*).
// ---------------------------------------------------------------------------
__global__ __launch_bounds__(256) void ln_rows(
    const float* __restrict__ src, float* __restrict__ dst,
    __nv_bfloat16* __restrict__ hi, __nv_bfloat16* __restrict__ lo,
    const float* __restrict__ g, const float* __restrict__ be,
    int L, int Bb, int D, int srcBMajor, int dstBMajor, int outMode)
{
    __shared__ float shm[32];
    int r = blockIdx.x;
    int l = r / Bb, b = r % Bb;
    const float* s = src + (srcBMajor ? ((size_t)b * L + l) : (size_t)r) * D;
    size_t drow = (dstBMajor ? ((size_t)b * L + l) : (size_t)r) * D;

    float sum = 0.f;
    for (int i = 4 * threadIdx.x; i < D; i += 1024) {
        float4 v = *(const float4*)(s + i);
        sum += (v.x + v.y) + (v.z + v.w);
    }
    float mean = blockReduceSum(sum, shm) / (float)D;

    float vs = 0.f;
    for (int i = 4 * threadIdx.x; i < D; i += 1024) {
        float4 v = *(const float4*)(s + i);
        float a = v.x - mean, bq = v.y - mean, c = v.z - mean, e = v.w - mean;
        vs += a * a + bq * bq + c * c + e * e;
    }
    float var = blockReduceSum(vs, shm) / (float)D;
    float rstd = rsqrtf(var + LN_EPS);

    for (int i = 4 * threadIdx.x; i < D; i += 1024) {
        float4 v = *(const float4*)(s + i);
        float4 gv = *(const float4*)(g + i);
        float4 bv = *(const float4*)(be + i);
        float4 o;
        o.x = (v.x - mean) * rstd * gv.x + bv.x;
        o.y = (v.y - mean) * rstd * gv.y + bv.y;
        o.z = (v.z - mean) * rstd * gv.z + bv.z;
        o.w = (v.w - mean) * rstd * gv.w + bv.w;
        if (dst) *(float4*)(dst + drow + i) = o;
        if (outMode == 1) {
            __nv_bfloat16 h0v = __float2bfloat16(o.x);
            __nv_bfloat16 h1v = __float2bfloat16(o.y);
            __nv_bfloat16 h2v = __float2bfloat16(o.z);
            __nv_bfloat16 h3v = __float2bfloat16(o.w);
            __nv_bfloat162* hp = (__nv_bfloat162*)(hi + drow + i);
            __nv_bfloat162* lp = (__nv_bfloat162*)(lo + drow + i);
            hp[0] = __nv_bfloat162(h0v, h1v);
            hp[1] = __nv_bfloat162(h2v, h3v);
            lp[0] = __nv_bfloat162(
                __float2bfloat16(o.x - __bfloat162float(h0v)),
                __float2bfloat16(o.y - __bfloat162float(h1v)));
            lp[1] = __nv_bfloat162(
                __float2bfloat16(o.z - __bfloat162float(h2v)),
                __float2bfloat16(o.w - __bfloat162float(h3v)));
        } else if (outMode == 2) {
            __half2* hp = (__half2*)((__half*)hi + drow + i);
            hp[0] = __floats2half2_rn(o.x, o.y);
            hp[1] = __floats2half2_rn(o.z, o.w);
        }
    }
}

// ---------------------------------------------------------------------------
// fp16 split conversion (for Wih): fp32 -> (fp16 hi, fp16 lo)
// ---------------------------------------------------------------------------
__global__ void conv_split_f16(const float* __restrict__ x,
                               __half* __restrict__ hi,
                               __half* __restrict__ lo, int n)
{
    int i = blockIdx.x * blockDim.x + threadIdx.x;
    if (i >= n) return;
    float v = x[i];
    __half h = __float2half(v);
    hi[i] = h;
    lo[i] = __float2half(v - __half2float(h));
}

// W[K][N] -> Bh/Bl [Npad][K]; f16 flag selects fp16 vs bf16 split.
__global__ void transpose_split(const float* __restrict__ W,
                                __nv_bfloat16* __restrict__ Bh,
                                __nv_bfloat16* __restrict__ Bl,
                                int K, int N, int f16)
{
    __shared__ float t[32][33];
    int n0 = blockIdx.x * 32, k0 = blockIdx.y * 32;
    int x = threadIdx.x, y = threadIdx.y;
    #pragma unroll
    for (int j = 0; j < 32; j += 8) {
        int k = k0 + y + j, n = n0 + x;
        t[y + j][x] = (n < N) ? W[(size_t)k * N + n] : 0.f;
    }
    __syncthreads();
    #pragma unroll
    for (int j = 0; j < 32; j += 8) {
        int n = n0 + y + j, k = k0 + x;
        float v = t[x][y + j];
        size_t idx = (size_t)n * K + k;
        if (f16) {
            __half h = __float2half(v);
            ((__half*)Bh)[idx] = h;
            ((__half*)Bl)[idx] = __float2half(v - __half2float(h));
        } else {
            __nv_bfloat16 h = __float2bfloat16(v);
            Bh[idx] = h;
            Bl[idx] = __float2bfloat16(v - __bfloat162float(h));
        }
    }
}

// ---------------------------------------------------------------------------
// Split-bf16 GEMM via mma.sync — PROVEN R11 config. DO NOT restructure
// (R12/R14 regressions: issue-latency bound, tensor% tracks warps/SM).
// ---------------------------------------------------------------------------
#define GS_A_LO  6144
#define GS_B_HI  12288
#define GS_B_LO  18432
#define GS_STAGE 24576

__global__ __launch_bounds__(256) void gemm_mma(
    const __nv_bfloat16* __restrict__ Ah, const __nv_bfloat16* __restrict__ Al,
    const __nv_bfloat16* __restrict__ Bh, const __nv_bfloat16* __restrict__ Bl,
    const float* __restrict__ bias, float* __restrict__ C,
    int K, int Nreal, int ldC)
{
    extern __shared__ char smem[];
    const uint32_t sb = smem_to_u32(smem);
    const int tid = threadIdx.x, warp = tid >> 5, lane = tid & 31;
    const int n0 = blockIdx.x * 128, m0 = blockIdx.y * 128;
    const int warpM = warp >> 2, warpN = warp & 3;      // 2 x 4
    const int S = K >> 4;                                // BK = 16

    float d[4][4][4];
    #pragma unroll
    for (int mt = 0; mt < 4; mt++)
        #pragma unroll
        for (int nt = 0; nt < 4; nt++)
            #pragma unroll
            for (int e = 0; e < 4; e++) d[mt][nt][e] = 0.f;

    const int lrow = tid >> 1, lc = tid & 1;
    auto load_stage = [&](int s, int buf) {
        const size_t kc = ((size_t)s << 4) + lc * 8;
        uint32_t so = (uint32_t)buf * GS_STAGE + lrow * 48 + lc * 16;
        size_t ga = (size_t)(m0 + lrow) * K + kc;
        size_t gb = (size_t)(n0 + lrow) * K + kc;
        cp_async16(sb + so,           Ah + ga);
        cp_async16(sb + so + GS_A_LO, Al + ga);
        cp_async16(sb + so + GS_B_HI, Bh + gb);
        cp_async16(sb + so + GS_B_LO, Bl + gb);
        CP_COMMIT();
    };

    load_stage(0, 0);
    load_stage(1, 1);
    load_stage(2, 2);

    const uint32_t off = (uint32_t)(lane & 15) * 48 + (uint32_t)(lane >> 4) * 16;

    for (int s = 0; s < S; s++) {
        if (s <= S - 3)      CP_WAIT(2);
        else if (s == S - 2) CP_WAIT(1);
        else                 CP_WAIT(0);
        __syncthreads();
        if (s + 3 < S) load_stage(s + 3, (s + 3) & 3);

        const uint32_t base  = sb + (uint32_t)(s & 3) * GS_STAGE;
        const uint32_t aBase = base + (uint32_t)(warpM * 64) * 48;
        const uint32_t bBase = base + GS_B_HI + (uint32_t)(warpN * 32) * 48;

        uint32_t aH[4][4], aL[4][4], bH[2][4], bL[2][4];
        #pragma unroll
        for (int mt = 0; mt < 4; mt++) {
            uint32_t ad = aBase + (uint32_t)(mt * 16) * 48 + off;
            ldm_x4(aH[mt], ad);
            ldm_x4(aL[mt], ad + GS_A_LO);
        }
        #pragma unroll
        for (int ng = 0; ng < 2; ng++) {
            uint32_t bd = bBase + (uint32_t)(ng * 16) * 48 + off;
            ldm_x4(bH[ng], bd);
            ldm_x4(bL[ng], bd + (GS_B_LO - GS_B_HI));
        }
        #pragma unroll
        for (int mt = 0; mt < 4; mt++)
            #pragma unroll
            for (int ng = 0; ng < 2; ng++) {
                mma_bf16(d[mt][2 * ng],     aH[mt], bH[ng][0], bH[ng][2]);
                mma_bf16(d[mt][2 * ng + 1], aH[mt], bH[ng][1], bH[ng][3]);
                mma_bf16(d[mt][2 * ng],     aH[mt], bL[ng][0], bL[ng][2]);
                mma_bf16(d[mt][2 * ng + 1], aH[mt], bL[ng][1], bL[ng][3]);
                mma_bf16(d[mt][2 * ng],     aL[mt], bH[ng][0], bH[ng][2]);
                mma_bf16(d[mt][2 * ng + 1], aL[mt], bH[ng][1], bH[ng][3]);
            }
    }

    const int r0 = m0 + warpM * 64 + (lane >> 2);
    const int c0 = n0 + warpN * 32 + (lane & 3) * 2;
    const bool vec = ((ldC & 1) == 0);
    #pragma unroll
    for (int mt = 0; mt < 4; mt++) {
        #pragma unroll
        for (int nt = 0; nt < 4; nt++) {
            int cc = c0 + nt * 8;
            float* p0 = C + (size_t)(r0 + mt * 16) * ldC;
            float* p1 = p0 + 8 * (size_t)ldC;
            if (vec && cc + 1 < Nreal) {
                float b0v = bias ? bias[cc] : 0.f;
                float b1v = bias ? bias[cc + 1] : 0.f;
                *(float2*)(p0 + cc) = make_float2(d[mt][nt][0] + b0v, d[mt][nt][1] + b1v);
                *(float2*)(p1 + cc) = make_float2(d[mt][nt][2] + b0v, d[mt][nt][3] + b1v);
            } else {
                if (cc < Nreal) {
                    float bv = bias ? bias[cc] : 0.f;
                    p0[cc] = d[mt][nt][0] + bv;
                    p1[cc] = d[mt][nt][2] + bv;
                }
                if (cc + 1 < Nreal) {
                    float bv = bias ? bias[cc + 1] : 0.f;
                    p0[cc + 1] = d[mt][nt][1] + bv;
                    p1[cc + 1] = d[mt][nt][3] + bv;
                }
            }
        }
    }
}

// ---------------------------------------------------------------------------
// 2-product fp16 GEMM: D = Ah*(Bh+Bl). Used ONLY for LSTM-pre + projection
// (error ~2.4e-4 injected there passes through <=1 contraction). Same proven
// schedule, 3 operand arrays.
// ---------------------------------------------------------------------------
#define G2_B_HI  6144
#define G2_B_LO  12288
#define G2_STAGE 18432

__global__ __launch_bounds__(256) void gemm_f16(
    const __half* __restrict__ Ah,
    const __half* __restrict__ Bh, const __half* __restrict__ Bl,
    const float* __restrict__ bias, float* __restrict__ C,
    int K, int Nreal, int ldC)
{
    extern __shared__ char smem[];
    const uint32_t sb = smem_to_u32(smem);
    const int tid = threadIdx.x, warp = tid >> 5, lane = tid & 31;
    const int n0 = blockIdx.x * 128, m0 = blockIdx.y * 128;
    const int warpM = warp >> 2, warpN = warp & 3;
    const int S = K >> 4;

    float d[4][4][4];
    #pragma unroll
    for (int mt = 0; mt < 4; mt++)
        #pragma unroll
        for (int nt = 0; nt < 4; nt++)
            #pragma unroll
            for (int e = 0; e < 4; e++) d[mt][nt][e] = 0.f;

    const int lrow = tid >> 1, lc = tid & 1;
    auto load_stage = [&](int s, int buf) {
        const size_t kc = ((size_t)s << 4) + lc * 8;
        uint32_t so = (uint32_t)buf * G2_STAGE + lrow * 48 + lc * 16;
        size_t ga = (size_t)(m0 + lrow) * K + kc;
        size_t gb = (size_t)(n0 + lrow) * K + kc;
        cp_async16(sb + so,           Ah + ga);
        cp_async16(sb + so + G2_B_HI, Bh + gb);
        cp_async16(sb + so + G2_B_LO, Bl + gb);
        CP_COMMIT();
    };

    load_stage(0, 0);
    load_stage(1, 1);
    load_stage(2, 2);

    const uint32_t off = (uint32_t)(lane & 15) * 48 + (uint32_t)(lane >> 4) * 16;

    for (int s = 0; s < S; s++) {
        if (s <= S - 3)      CP_WAIT(2);
        else if (s == S - 2) CP_WAIT(1);
        else                 CP_WAIT(0);
        __syncthreads();
        if (s + 3 < S) load_stage(s + 3, (s + 3) & 3);

        const uint32_t base  = sb + (uint32_t)(s & 3) * G2_STAGE;
        const uint32_t aBase = base + (uint32_t)(warpM * 64) * 48;
        const uint32_t bBase = base + G2_B_HI + (uint32_t)(warpN * 32) * 48;

        uint32_t aH[4][4], bH[2][4], bL[2][4];
        #pragma unroll
        for (int mt = 0; mt < 4; mt++) {
            uint32_t ad = aBase + (uint32_t)(mt * 16) * 48 + off;
            ldm_x4(aH[mt], ad);
        }
        #pragma unroll
        for (int ng = 0; ng < 2; ng++) {
            uint32_t bd = bBase + (uint32_t)(ng * 16) * 48 + off;
            ldm_x4(bH[ng], bd);
            ldm_x4(bL[ng], bd + (G2_B_LO - G2_B_HI));
        }
        #pragma unroll
        for (int mt = 0; mt < 4; mt++)
            #pragma unroll
            for (int ng = 0; ng < 2; ng++) {
                mma_f16(d[mt][2 * ng],     aH[mt], bH[ng][0], bH[ng][2]);
                mma_f16(d[mt][2 * ng + 1], aH[mt], bH[ng][1], bH[ng][3]);
                mma_f16(d[mt][2 * ng],     aH[mt], bL[ng][0], bL[ng][2]);
                mma_f16(d[mt][2 * ng + 1], aH[mt], bL[ng][1], bL[ng][3]);
            }
    }

    const int r0 = m0 + warpM * 64 + (lane >> 2);
    const int c0 = n0 + warpN * 32 + (lane & 3) * 2;
    const bool vec = ((ldC & 1) == 0);
    #pragma unroll
    for (int mt = 0; mt < 4; mt++) {
        #pragma unroll
        for (int nt = 0; nt < 4; nt++) {
            int cc = c0 + nt * 8;
            float* p0 = C + (size_t)(r0 + mt * 16) * ldC;
            float* p1 = p0 + 8 * (size_t)ldC;
            if (vec && cc + 1 < Nreal) {
                float b0v = bias ? bias[cc] : 0.f;
                float b1v = bias ? bias[cc + 1] : 0.f;
                *(float2*)(p0 + cc) = make_float2(d[mt][nt][0] + b0v, d[mt][nt][1] + b1v);
                *(float2*)(p1 + cc) = make_float2(d[mt][nt][2] + b0v, d[mt][nt][3] + b1v);
            } else {
                if (cc < Nreal) {
                    float bv = bias ? bias[cc] : 0.f;
                    p0[cc] = d[mt][nt][0] + bv;
                    p1[cc] = d[mt][nt][2] + bv;
                }
                if (cc + 1 < Nreal) {
                    float bv = bias ? bias[cc + 1] : 0.f;
                    p0[cc + 1] = d[mt][nt][1] + bv;
                    p1[cc + 1] = d[mt][nt][3] + bv;
                }
            }
        }
    }
}

// ---------------------------------------------------------------------------
// SRU scan (R11 proven form). Optional fp16 output (pre-LSTM layer).
// ---------------------------------------------------------------------------
__global__ void sru_scan(
    const float* __restrict__ U, const float* __restrict__ res,
    const float* __restrict__ vc, const float* __restrict__ bias,
    float* __restrict__ out,
    __half* __restrict__ hi,
    int L, int Bb, int H, int k)
{
    int idx = blockIdx.x * blockDim.x + threadIdx.x;
    if (idx >= Bb * H) return;
    int hh = idx % H, b = idx / H;
    float vfn = -vc[hh], vrn = -vc[H + hh];
    float bf = bias[hh], br = bias[H + hh];
    float c = 0.f;

    size_t ustep = (size_t)Bb * k * H;
    size_t ubase = (size_t)b * k * H + hh;
    size_t ostep = (size_t)Bb * H;
    size_t obase = (size_t)b * H + hh;

    const float* u  = U + ubase;
    const float* rp = (k == 3) ? (res + obase) : (U + ubase + 3 * (size_t)H);
    size_t rstep    = (k == 3) ? ostep : ustep;
    float* o = out + obase;

    float pa0[16], pa1[16], pa2[16], prt[16];
    #pragma unroll
    for (int j = 0; j < 16; j++) {
        size_t uo = (size_t)j * ustep;
        pa0[j] = __ldcs(u + uo);
        pa1[j] = -(__ldcs(u + uo + H) + bf);
        pa2[j] = -(__ldcs(u + uo + 2 * (size_t)H) + br);
        prt[j] = __ldcs(rp + (size_t)j * rstep);
    }

    #pragma unroll 16
    for (int t = 0; t < L; ++t) {
        int j = t & 15;
        float a0 = pa0[j], a1n = pa1[j], a2n = pa2[j], rt = prt[j];
        int tn = (t + 16 < L) ? (t + 16) : (L - 1);
        size_t uo = (size_t)tn * ustep;
        pa0[j] = __ldcs(u + uo);
        pa1[j] = -(__ldcs(u + uo + H) + bf);
        pa2[j] = -(__ldcs(u + uo + 2 * (size_t)H) + br);
        prt[j] = __ldcs(rp + (size_t)tn * rstep);

        float e1 = __expf(fmaf(vfn, c, a1n));
        float f  = __fdividef(1.f, 1.f + e1);
        float e2 = __expf(fmaf(vrn, c, a2n));
        float r  = __fdividef(1.f, 1.f + e2);
        c = fmaf(f, c - a0, a0);
        float ov = fmaf(r, c - rt, rt);
        o[(size_t)t * ostep] = ov;
        if (hi) hi[obase + (size_t)t * ostep] = __float2half(ov);
    }
}

__global__ void pool2(const float* __restrict__ in, float* __restrict__ out, int n)
{
    int i = blockIdx.x * blockDim.x + threadIdx.x;
    if (i >= n) return;
    int lp = i >> 14;
    size_t j = (size_t)i + (size_t)lp * 16384;
    out[i] = 0.5f * (in[j] + in[j + 16384]);
}

__global__ void addvec(const float* __restrict__ a, const float* __restrict__ b,
                       float* __restrict__ o, int n)
{
    int i = blockIdx.x * blockDim.x + threadIdx.x;
    if (i < n) o[i] = a[i] + b[i];
}

__global__ void lstm_init(float* h0)
{
    int i = blockIdx.x * blockDim.x + threadIdx.x;
    if (i < 16384) h0[i] = 0.f;
    if (i == 0) g_bar_count = 0u;
}

// ---------------------------------------------------------------------------
// Persistent LSTM (148 CTAs). f32x2 packed fma; cp.async h staging;
// monotonic red.global barrier.
// ---------------------------------------------------------------------------
__global__ __launch_bounds__(256) void lstm_persist(
    const float* __restrict__ pre, const float* __restrict__ Whh,
    const float* __restrict__ h0, float* __restrict__ hout)
{
    extern __shared__ float hs[];
    const ulonglong2* hs2 = (const ulonglong2*)hs;
    const uint32_t hs_sb = smem_to_u32(hs);
    const int tid = threadIdx.x, bid = blockIdx.x;
    const int warp = tid >> 5, lane = tid & 31;

    int cnt, s;
    if (bid < 136) { cnt = 7; s = bid * 7; }
    else           { cnt = 6; s = 952 + (bid - 136) * 6; }
    const bool active = warp < cnt;
    const int hh = s + (active ? warp : 0);

    const ulonglong2* W2[4];
    #pragma unroll
    for (int g = 0; g < 4; g++)
        W2[g] = (const ulonglong2*)(Whh + ((size_t)g * 1024 + hh) * 1024);

    unsigned* barp;
    { unsigned* t; asm("cvta.global.u64 %0, %1;" : "=l"(t) : "l"(&g_bar_count)); barp = t; }

    float c = 0.f;

    for (int t = 0; t < 512; t++) {
        const float* hsrc = (t == 0) ? h0 : (hout + (size_t)(t - 1) * 16384);

        __syncthreads();

        #pragma unroll
        for (int half = 0; half < 2; half++) {
            #pragma unroll
            for (int j2 = 0; j2 < 8; j2++) {
                int cidx = tid + j2 * 256;
                int b = cidx >> 7, kc = cidx & 127;
                uint32_t foff = (uint32_t)(b * 1024 + half * 512 + kc * 4);
                cp_async16(hs_sb + foff * 4, hsrc + foff);
            }
            CP_COMMIT();
        }

        float pv0 = 0.f, pv1 = 0.f, pv2 = 0.f, pv3 = 0.f;
        if (active && lane < 16) {
            const float* pb = pre + (size_t)t * 65536 + (size_t)lane * 4096;
            pv0 = __ldcg(pb + hh);
            pv1 = __ldcg(pb + 1024 + hh);
            pv2 = __ldcg(pb + 2048 + hh);
            pv3 = __ldcg(pb + 3072 + hh);
        }

        unsigned long long acc2[4][16];
        #pragma unroll
        for (int g = 0; g < 4; g++)
            #pragma unroll
            for (int b = 0; b < 16; b++) acc2[g][b] = 0ull;

        CP_WAIT(1);
        __syncthreads();
        if (active) {
            #pragma unroll 1
            for (int i = lane; i < 128; i += 32) {
                ulonglong2 wq[4];
                #pragma unroll
                for (int g = 0; g < 4; g++) wq[g] = W2[g][i];
                #pragma unroll
                for (int b = 0; b < 16; b++) {
                    ulonglong2 hq = hs2[b * 256 + i];
                    #pragma unroll
                    for (int g = 0; g < 4; g++) {
                        fma_f32x2(acc2[g][b], wq[g].x, hq.x);
                        fma_f32x2(acc2[g][b], wq[g].y, hq.y);
                    }
                }
            }
        }
        CP_WAIT(0);
        __syncthreads();
        if (active) {
            #pragma unroll 1
            for (int i = 128 + lane; i < 256; i += 32) {
                ulonglong2 wq[4];
                #pragma unroll
                for (int g = 0; g < 4; g++) wq[g] = W2[g][i];
                #pragma unroll
                for (int b = 0; b < 16; b++) {
                    ulonglong2 hq = hs2[b * 256 + i];
                    #pragma unroll
                    for (int g = 0; g < 4; g++) {
                        fma_f32x2(acc2[g][b], wq[g].x, hq.x);
                        fma_f32x2(acc2[g][b], wq[g].y, hq.y);
                    }
                }
            }

            float gate[4] = {0.f, 0.f, 0.f, 0.f};
            #pragma unroll
            for (int g = 0; g < 4; g++)
                #pragma unroll
                for (int b = 0; b < 16; b++) {
                    F2U u2; u2.u = acc2[g][b];
                    float v = u2.f.x + u2.f.y;
                    #pragma unroll
                    for (int o = 16; o; o >>= 1)
                        v += __shfl_xor_sync(0xffffffffu, v, o);
                    if (lane == b) gate[g] = v;
                }

            if (lane < 16) {
                float ig = sigf(gate[0] + pv0);
                float fg = sigf(gate[1] + pv1);
                float gg = tanhf(gate[2] + pv2);
                float og = sigf(gate[3] + pv3);
                c = fg * c + ig * gg;
                float hv = og * tanhf(c);
                hout[(size_t)t * 16384 + lane * 1024 + hh] = hv;
            }
        }

        __syncthreads();
        if (tid == 0) {
            __threadfence();
            asm volatile("red.global.add.u32 [%0], %1;" :: "l"(barp), "r"(1u) : "memory");
            unsigned target = 148u * (unsigned)(t + 1);
            unsigned v;
            do {
                asm volatile("ld.global.cg.u32 %0, [%1];" : "=r"(v) : "l"(barp) : "memory");
                if (v >= target) break;
                __nanosleep(32);
            } while (true);
            __threadfence();
        }
    }
}

// ---------------------------------------------------------------------------
// Orchestration
// ---------------------------------------------------------------------------
extern "C" void kernel_launch(void* const* d_in, const int* in_sizes, int n_in,
                              void* d_out, int out_size)
{
    const float* x    = (const float*)d_in[0];
    const float* w0   = (const float*)d_in[1];
    const float* vc0  = (const float*)d_in[2];
    const float* b0   = (const float*)d_in[3];
    const float* g0   = (const float*)d_in[4];
    const float* be0  = (const float*)d_in[5];
    const float* Ws   = (const float*)d_in[6];
    const float* VCs  = (const float*)d_in[7];
    const float* Bsb  = (const float*)d_in[8];
    const float* Gs   = (const float*)d_in[9];
    const float* Bes  = (const float*)d_in[10];
    const float* Wih  = (const float*)d_in[11];
    const float* Whh  = (const float*)d_in[12];
    const float* bih  = (const float*)d_in[13];
    const float* bhh  = (const float*)d_in[14];
    const float* gh   = (const float*)d_in[15];
    const float* bhv  = (const float*)d_in[16];
    const float* Wout = (const float*)d_in[17];
    float* out = (float*)d_out;

    float *xn, *U, *hA, *hB, *bsum, *h0;
    __nv_bfloat16 *Ah, *Al, *Bh, *Bl;
    cudaGetSymbolAddress((void**)&xn,   g_xn);
    cudaGetSymbolAddress((void**)&U,    g_U);
    cudaGetSymbolAddress((void**)&hA,   g_hA);
    cudaGetSymbolAddress((void**)&hB,   g_hB);
    cudaGetSymbolAddress((void**)&bsum, g_bsum);
    cudaGetSymbolAddress((void**)&h0,   g_h0);
    cudaGetSymbolAddress((void**)&Ah,   g_Ah);
    cudaGetSymbolAddress((void**)&Al,   g_Al);
    cudaGetSymbolAddress((void**)&Bh,   g_Bh);
    cudaGetSymbolAddress((void**)&Bl,   g_Bl);
    __half* Ah16 = (__half*)Ah;
    __half* Bh16 = (__half*)Bh;
    __half* Bl16 = (__half*)Bl;

    cudaFuncSetAttribute(lstm_persist, cudaFuncAttributeMaxDynamicSharedMemorySize, 65536);
    cudaFuncSetAttribute(gemm_mma,    cudaFuncAttributeMaxDynamicSharedMemorySize, 4 * GS_STAGE);
    cudaFuncSetAttribute(gemm_f16,    cudaFuncAttributeMaxDynamicSharedMemorySize, 4 * G2_STAGE);

    const int B = 16, H = 1024;
    const int GSM  = 4 * GS_STAGE;
    const int GSM2 = 4 * G2_STAGE;

    // addvec first so the first gemm_mma lands in the profiled launch slot.
    addvec<<<16, 256>>>(bih, bhh, bsum, 4096);

    // ---- SRU layer 0: (B,1024,128) -> (1024,B,1024) ----
    ln_rows<<<16384, 256>>>(x, nullptr, Ah, Al, g0, be0, 1024, B, 128, 1, 0, 1);
    { dim3 g(4096 / 32, 128 / 32); dim3 bl(32, 8);
      transpose_split<<<g, bl>>>(w0, Bh, Bl, 128, 4096, 0); }
    { dim3 g(32, 128); gemm_mma<<<g, 256, GSM>>>(Ah, Al, Bh, Bl, nullptr, U, 128, 4096, 4096); }
    sru_scan<<<256, 64>>>(U, nullptr, vc0, b0, hA, nullptr, 1024, B, H, 4);

    float* cur = hA; float* alt = hB;

    // ---- SRU layers 1-3 (L=1024) ----
    for (int i = 0; i < 3; i++) {
        ln_rows<<<16384, 256>>>(cur, xn, Ah, Al, Gs + i * H, Bes + i * H, 1024, B, H, 0, 0, 1);
        { dim3 g(3072 / 32, 1024 / 32); dim3 bl(32, 8);
          transpose_split<<<g, bl>>>(Ws + (size_t)i * H * 3072, Bh, Bl, 1024, 3072, 0); }
        { dim3 g(24, 128); gemm_mma<<<g, 256, GSM>>>(Ah, Al, Bh, Bl, nullptr, U, 1024, 3072, 3072); }
        sru_scan<<<256, 64>>>(U, xn, VCs + i * 2048, Bsb + i * 2048, alt, nullptr, 1024, B, H, 3);
        float* t2 = cur; cur = alt; alt = t2;
    }

    // ---- time pooling 1024 -> 512 ----
    pool2<<<32768, 256>>>(cur, alt, 512 * 16 * 1024);
    { float* t2 = cur; cur = alt; alt = t2; }

    // ---- SRU layers 4-6 (L=512); layer 6 also emits fp16 A for LSTM-pre ----
    for (int i = 3; i < 6; i++) {
        ln_rows<<<8192, 256>>>(cur, xn, Ah, Al, Gs + i * H, Bes + i * H, 512, B, H, 0, 0, 1);
        { dim3 g(3072 / 32, 1024 / 32); dim3 bl(32, 8);
          transpose_split<<<g, bl>>>(Ws + (size_t)i * H * 3072, Bh, Bl, 1024, 3072, 0); }
        { dim3 g(24, 64); gemm_mma<<<g, 256, GSM>>>(Ah, Al, Bh, Bl, nullptr, U, 1024, 3072, 3072); }
        if (i == 5)
            sru_scan<<<256, 64>>>(U, xn, VCs + i * 2048, Bsb + i * 2048, alt, Ah16, 512, B, H, 3);
        else
            sru_scan<<<256, 64>>>(U, xn, VCs + i * 2048, Bsb + i * 2048, alt, nullptr, 512, B, H, 3);
        float* t2 = cur; cur = alt; alt = t2;
    }

    // ---- LSTM: pre-GEMM in 2-product fp16 (A fp16 from layer-6 scan) ----
    conv_split_f16<<<16384, 256>>>(Wih, Bh16, Bl16, 4096 * 1024);
    { dim3 g(32, 64); gemm_f16<<<g, 256, GSM2>>>(Ah16, Bh16, Bl16, bsum, U, 1024, 4096, 4096); }
    lstm_init<<<64, 256>>>(h0);
    lstm_persist<<<148, 256, 65536>>>(U, Whh, h0, alt);

    // ---- final LN (fp16 out, (b,l)-major) + 2-product fp16 projection ----
    ln_rows<<<8192, 256>>>(alt, nullptr, Ah, nullptr, gh, bhv, 512, B, H, 0, 1, 2);
    { dim3 g(1024 / 32, 1024 / 32); dim3 bl(32, 8);
      transpose_split<<<g, bl>>>(Wout, Bh, Bl, 1024, 1001, 1); }
    { dim3 g(8, 64); gemm_f16<<<g, 256, GSM2>>>(Ah16, Bh16, Bl16, nullptr, out, 1024, 1001, 1001); }
}